// round 15
// baseline (speedup 1.0000x reference)
#include <cuda_runtime.h>
#include <cuda_fp16.h>

#define N_NODES 50000
#define N_EDGES 800000
#define IN_CH   128
#define HID     64
#define HID2    32
#define NB      196                        // scan blocks (256 nodes each)
#define EBLK    3125                       // edge blocks of 256

// ---------------- scratch (device globals; no allocations allowed) ----------
__device__ int      g_cnt  [N_NODES];
__device__ int      g_lex  [N_NODES];
__device__ int      g_bsum [NB];
__device__ int      g_start[N_NODES];
__device__ int      g_rank [N_EDGES];      // edge rank within its target bucket
__device__ unsigned g_csr  [N_EDGES];      // {src:16 | fp16(dinv[src]):16}
__device__ int      g_is64;
__device__ __half2  g_h1h [N_NODES * 32];  // raw x @ W1, fp16 (64 ch as 32 half2)
__device__ __half2  g_a1h [N_NODES * 32];  // agg1 output, fp16 (64 ch as 32 half2)
__device__ __half2  g_h2h [N_NODES * 16];  // (h2 * dinv), fp16 (32 ch as 16 half2)
__device__ float    g_s1[HID],  g_t1[HID]; // folded bias+BN affine, layer 1
__device__ float    g_s2[HID2], g_t2[HID2];

// ---------------- K0: detect dtype + zero counts + folded BN affines --------
// NOTE: zeroing g_cnt here (immediately before convert's atomics) keeps the
// array L2-resident and dirty — tail-zeroing it elsewhere cost ~45us (R5/R6).
__global__ __launch_bounds__(256) void k0_kernel(const unsigned int* __restrict__ w,
    const float* __restrict__ b1, const float* __restrict__ rm1,
    const float* __restrict__ rv1, const float* __restrict__ g1,
    const float* __restrict__ be1,
    const float* __restrict__ b2, const float* __restrict__ rm2,
    const float* __restrict__ rv2, const float* __restrict__ g2,
    const float* __restrict__ be2) {
    int bb = blockIdx.x;
    if (bb == NB) {   // int64 indices in [0,50000) have zero high words
        __shared__ int cnt;
        if (threadIdx.x == 0) cnt = 0;
        __syncthreads();
        int local = 0;
        for (int i = threadIdx.x; i < 2048; i += 256)
            if (w[2 * i + 1] != 0u) local++;
        atomicAdd(&cnt, local);
        __syncthreads();
        if (threadIdx.x == 0) g_is64 = (cnt < 100) ? 1 : 0;
        return;
    }
    int i = bb * 256 + threadIdx.x;
    if (i < N_NODES) g_cnt[i] = 0;
    if (bb == 0) {
        int t = threadIdx.x;
        if (t < HID) {
            float s = g1[t] * rsqrtf(rv1[t] + 1e-5f);
            g_s1[t] = s;
            g_t1[t] = (b1[t] - rm1[t]) * s + be1[t];
        } else if (t < HID + HID2) {
            int c = t - HID;
            float s = g2[c] * rsqrtf(rv2[c] + 1e-5f);
            g_s2[c] = s;
            g_t2[c] = (b2[c] - rm2[c]) * s + be2[c];
        }
    }
}

// ---------------- histogram over target nodes + per-edge rank ---------------
__global__ __launch_bounds__(256) void convert_kernel(const void* __restrict__ ei) {
    int e = blockIdx.x * 256 + threadIdx.x;
    if (e >= N_EDGES) return;
    int c = g_is64 ? (int)((const long long*)ei)[N_EDGES + e]
                   : ((const int*)ei)[N_EDGES + e];
    g_rank[e] = atomicAdd(&g_cnt[c], 1);
}

// ---------------- scan1: per-block exclusive scan (warp shuffles) -----------
__global__ __launch_bounds__(256) void scan1_kernel() {
    __shared__ int wsum[8];
    int tid = threadIdx.x;
    int lane = tid & 31, wrp = tid >> 5;
    int i = blockIdx.x * 256 + tid;
    int v = (i < N_NODES) ? g_cnt[i] : 0;
    int s = v;
#pragma unroll
    for (int off = 1; off < 32; off <<= 1) {
        int u = __shfl_up_sync(0xffffffffu, s, off);
        if (lane >= off) s += u;
    }
    if (lane == 31) wsum[wrp] = s;
    __syncthreads();
    if (tid < 32) {
        int ws_ = (tid < 8) ? wsum[tid] : 0;
#pragma unroll
        for (int off = 1; off < 8; off <<= 1) {
            int u = __shfl_up_sync(0xffffffffu, ws_, off);
            if (tid >= off) ws_ += u;
        }
        if (tid < 8) wsum[tid] = ws_;
    }
    __syncthreads();
    int incl = s + (wrp > 0 ? wsum[wrp - 1] : 0);
    if (i < N_NODES) g_lex[i] = incl - v;
    if (tid == 255) g_bsum[blockIdx.x] = incl;
}

// ---------------- build: atomic-free CSR placement + start persist ----------
__global__ __launch_bounds__(256) void build_kernel(const void* __restrict__ ei) {
    __shared__ int s[256];
    int t = threadIdx.x;
    s[t] = (t < NB) ? g_bsum[t] : 0;
    __syncthreads();
#pragma unroll
    for (int off = 1; off < 256; off <<= 1) {
        int u = (t >= off) ? s[t - off] : 0;
        __syncthreads();
        s[t] += u;
        __syncthreads();
    }
    if (blockIdx.x < NB) {
        int i = blockIdx.x * 256 + t;
        if (i < N_NODES) {
            int boff = (blockIdx.x == 0) ? 0 : s[blockIdx.x - 1];
            g_start[i] = g_lex[i] + boff;
        }
    }
    int e = blockIdx.x * 256 + t;
    if (e >= N_EDGES) return;
    int r, c;
    if (g_is64) {
        const long long* p = (const long long*)ei;
        r = (int)p[e];
        c = (int)p[N_EDGES + e];
    } else {
        const int* p = (const int*)ei;
        r = p[e];
        c = p[N_EDGES + e];
    }
    int cb = c >> 8;
    int start = g_lex[c] + (cb ? s[cb - 1] : 0);
    __half wh = __float2half(rsqrtf(1.0f + (float)g_cnt[r]));
    unsigned packed = ((unsigned)r << 16) | (unsigned)__half_as_ushort(wh);
    g_csr[start + g_rank[e]] = packed;
}

// ---------------- GEMM1: h1h = fp16(x @ W1)  (side stream) ------------------
// BM=64 BN=64 BK=32, 256 threads, 4x4 microtile. xst padded to 65 cols.
__global__ __launch_bounds__(256) void gemm1_kernel(const float* __restrict__ x,
                                                    const float* __restrict__ W1) {
    __shared__ float xst[32][65];
    __shared__ float ws [32][64];
    int tid = threadIdx.x;
    int tx = tid & 15, ty = tid >> 4;
    int m0 = blockIdx.x * 64;
    float acc[4][4] = {};

    for (int kb = 0; kb < 4; kb++) {
#pragma unroll
        for (int q = 0; q < 2; q++) {
            int id = tid + q * 256;
            int ml = id >> 3;
            int k4 = id & 7;
            int row = m0 + ml;
            float4 v = make_float4(0.f, 0.f, 0.f, 0.f);
            if (row < N_NODES)
                v = *(const float4*)&x[row * IN_CH + kb * 32 + k4 * 4];
            xst[k4 * 4 + 0][ml] = v.x;
            xst[k4 * 4 + 1][ml] = v.y;
            xst[k4 * 4 + 2][ml] = v.z;
            xst[k4 * 4 + 3][ml] = v.w;
        }
#pragma unroll
        for (int q = 0; q < 2; q++) {
            int id = tid + q * 256;
            int kl = id >> 4;
            int n4 = id & 15;
            *(float4*)&ws[kl][n4 * 4] =
                *(const float4*)&W1[(kb * 32 + kl) * HID + n4 * 4];
        }
        __syncthreads();
#pragma unroll
        for (int kk = 0; kk < 32; kk++) {
            float av[4], bv[4];
            av[0] = xst[kk][ty * 4 + 0];
            av[1] = xst[kk][ty * 4 + 1];
            av[2] = xst[kk][ty * 4 + 2];
            av[3] = xst[kk][ty * 4 + 3];
            *(float4*)bv = *(const float4*)&ws[kk][tx * 4];
#pragma unroll
            for (int i = 0; i < 4; i++)
#pragma unroll
                for (int j = 0; j < 4; j++)
                    acc[i][j] += av[i] * bv[j];
        }
        __syncthreads();
    }
#pragma unroll
    for (int i = 0; i < 4; i++) {
        int row = m0 + ty * 4 + i;
        if (row < N_NODES) {
            __half2 a01 = __floats2half2_rn(acc[i][0], acc[i][1]);
            __half2 a23 = __floats2half2_rn(acc[i][2], acc[i][3]);
            *(uint2*)&g_h1h[row * 32 + tx * 2] =
                make_uint2(*(unsigned int*)&a01, *(unsigned int*)&a23);
        }
    }
}

// ---------------- edge helpers ----------------------------------------------
__device__ __forceinline__ void edge_unpack(unsigned e, int& src, float& w) {
    src = (int)(e >> 16);
    w   = __half2float(__ushort_as_half((unsigned short)e));
}

// ---------------- agg1: weighted fp16 gather over packed CSR ----------------
// One warp per node; lane owns 2 channels (one half2). CSR metadata read via
// uint2 vector loads (alignment peel on odd start); 8 gathers in flight.
__global__ __launch_bounds__(256) void agg1_kernel() {
    int n = (blockIdx.x * 256 + threadIdx.x) >> 5;
    int lane = threadIdx.x & 31;
    if (n >= N_NODES) return;
    int start = g_start[n];
    int deg   = g_cnt[n];
    float dn  = rsqrtf(1.0f + (float)deg);
    const __half2* __restrict__ h = g_h1h;
    float2 s = __half22float2(h[n * 32 + lane]);
    float2 acc = make_float2(s.x * dn, s.y * dn);
    int j = 0;
    // peel one edge so (start + j) is even -> uint2 loads are 8B aligned
    if ((start & 1) && deg > 0) {
        int src; float w;
        edge_unpack(g_csr[start], src, w);
        float2 v = __half22float2(h[src * 32 + lane]);
        acc.x += v.x * w;
        acc.y += v.y * w;
        j = 1;
    }
    for (; j + 8 <= deg; j += 8) {
        const uint2* q = (const uint2*)&g_csr[start + j];
        uint2 p0 = q[0], p1 = q[1], p2 = q[2], p3 = q[3];
        int s0, s1, s2, s3, s4, s5, s6, s7;
        float w0, w1, w2, w3, w4, w5, w6, w7;
        edge_unpack(p0.x, s0, w0); edge_unpack(p0.y, s1, w1);
        edge_unpack(p1.x, s2, w2); edge_unpack(p1.y, s3, w3);
        edge_unpack(p2.x, s4, w4); edge_unpack(p2.y, s5, w5);
        edge_unpack(p3.x, s6, w6); edge_unpack(p3.y, s7, w7);
        float2 v0 = __half22float2(h[s0 * 32 + lane]);
        float2 v1 = __half22float2(h[s1 * 32 + lane]);
        float2 v2 = __half22float2(h[s2 * 32 + lane]);
        float2 v3 = __half22float2(h[s3 * 32 + lane]);
        float2 v4 = __half22float2(h[s4 * 32 + lane]);
        float2 v5 = __half22float2(h[s5 * 32 + lane]);
        float2 v6 = __half22float2(h[s6 * 32 + lane]);
        float2 v7 = __half22float2(h[s7 * 32 + lane]);
        acc.x += v0.x * w0 + v1.x * w1 + v2.x * w2 + v3.x * w3 +
                 v4.x * w4 + v5.x * w5 + v6.x * w6 + v7.x * w7;
        acc.y += v0.y * w0 + v1.y * w1 + v2.y * w2 + v3.y * w3 +
                 v4.y * w4 + v5.y * w5 + v6.y * w6 + v7.y * w7;
    }
    for (; j + 2 <= deg; j += 2) {
        uint2 p = *(const uint2*)&g_csr[start + j];
        int s0, s1; float w0, w1;
        edge_unpack(p.x, s0, w0);
        edge_unpack(p.y, s1, w1);
        float2 v0 = __half22float2(h[s0 * 32 + lane]);
        float2 v1 = __half22float2(h[s1 * 32 + lane]);
        acc.x += v0.x * w0 + v1.x * w1;
        acc.y += v0.y * w0 + v1.y * w1;
    }
    if (j < deg) {
        int src; float w;
        edge_unpack(g_csr[start + j], src, w);
        float2 v = __half22float2(h[src * 32 + lane]);
        acc.x += v.x * w;
        acc.y += v.y * w;
    }
    g_a1h[n * 32 + lane] = __floats2half2_rn(acc.x * dn, acc.y * dn);
}

// ---------------- GEMM2: h2h = fp16((relu(a1h*s1+t1) @ W2) * dinv) ----------
// ast padded to 65 cols; agg1 input fp16 (uint2 = 4 channels per load).
__global__ __launch_bounds__(256) void gemm2_kernel(const float* __restrict__ W2) {
    __shared__ float ast[64][65];
    __shared__ float w2s[64][32];
    int tid = threadIdx.x;
    int tx = tid & 15, ty = tid >> 4;
    int m0 = blockIdx.x * 64;

#pragma unroll
    for (int q = 0; q < 4; q++) {
        int id = tid + q * 256;            // 1024 loads: 64 rows x 16 uint2
        int ml = id >> 4;
        int k4 = id & 15;                  // 4 channels per uint2
        int row = m0 + ml;
        float v[4] = {0.f, 0.f, 0.f, 0.f};
        if (row < N_NODES) {
            uint2 u = *(const uint2*)&g_a1h[row * 32 + k4 * 2];
            float2 f01 = __half22float2(*(__half2*)&u.x);
            float2 f23 = __half22float2(*(__half2*)&u.y);
            v[0] = f01.x; v[1] = f01.y; v[2] = f23.x; v[3] = f23.y;
        }
#pragma unroll
        for (int i = 0; i < 4; i++) {
            int k = k4 * 4 + i;
            float z = fmaxf(v[i] * g_s1[k] + g_t1[k], 0.0f);
            ast[k][ml] = (row < N_NODES) ? z : 0.0f;
        }
    }
#pragma unroll
    for (int q = 0; q < 2; q++) {
        int id = tid + q * 256;
        int kl = id >> 3;
        int n4 = id & 7;
        *(float4*)&w2s[kl][n4 * 4] = *(const float4*)&W2[kl * HID2 + n4 * 4];
    }
    __syncthreads();

    float acc[4][2] = {};
#pragma unroll
    for (int kk = 0; kk < 64; kk++) {
        float av[4], bv[2];
        av[0] = ast[kk][ty * 4 + 0];
        av[1] = ast[kk][ty * 4 + 1];
        av[2] = ast[kk][ty * 4 + 2];
        av[3] = ast[kk][ty * 4 + 3];
        *(float2*)bv = *(const float2*)&w2s[kk][tx * 2];
#pragma unroll
        for (int i = 0; i < 4; i++) {
            acc[i][0] += av[i] * bv[0];
            acc[i][1] += av[i] * bv[1];
        }
    }
#pragma unroll
    for (int i = 0; i < 4; i++) {
        int row = m0 + ty * 4 + i;
        if (row < N_NODES) {
            float d = rsqrtf(1.0f + (float)g_cnt[row]);
            g_h2h[row * 16 + tx] = __floats2half2_rn(acc[i][0] * d, acc[i][1] * d);
        }
    }
}

// ---------------- agg2 + BN/ReLU + fc, fused --------------------------------
// One warp per node; lane owns 1 channel; uint2 CSR loads with peel.
__global__ __launch_bounds__(256) void agg2_final_kernel(const float* __restrict__ fcW,
                                                         const float* __restrict__ fcb,
                                                         float* __restrict__ out) {
    int n = (blockIdx.x * 256 + threadIdx.x) >> 5;
    int lane = threadIdx.x & 31;
    if (n >= N_NODES) return;
    int start = g_start[n];
    int deg   = g_cnt[n];
    const __half* __restrict__ h = (const __half*)g_h2h;
    float acc = __half2float(h[n * 32 + lane]);   // self (already *dinv)
    int j = 0;
    if ((start & 1) && deg > 0) {
        acc += __half2float(h[(g_csr[start] >> 16) * 32 + lane]);
        j = 1;
    }
    for (; j + 8 <= deg; j += 8) {
        const uint2* q = (const uint2*)&g_csr[start + j];
        uint2 p0 = q[0], p1 = q[1], p2 = q[2], p3 = q[3];
        acc += ((__half2float(h[(p0.x >> 16) * 32 + lane]) + __half2float(h[(p0.y >> 16) * 32 + lane])) +
                (__half2float(h[(p1.x >> 16) * 32 + lane]) + __half2float(h[(p1.y >> 16) * 32 + lane]))) +
               ((__half2float(h[(p2.x >> 16) * 32 + lane]) + __half2float(h[(p2.y >> 16) * 32 + lane])) +
                (__half2float(h[(p3.x >> 16) * 32 + lane]) + __half2float(h[(p3.y >> 16) * 32 + lane])));
    }
    for (; j + 2 <= deg; j += 2) {
        uint2 p = *(const uint2*)&g_csr[start + j];
        acc += __half2float(h[(p.x >> 16) * 32 + lane]) +
               __half2float(h[(p.y >> 16) * 32 + lane]);
    }
    if (j < deg)
        acc += __half2float(h[(g_csr[start + j] >> 16) * 32 + lane]);
    float agg = acc * rsqrtf(1.0f + (float)deg);
    float v = fmaxf(agg * g_s2[lane] + g_t2[lane], 0.0f) * fcW[lane];
#pragma unroll
    for (int o = 16; o > 0; o >>= 1)
        v += __shfl_xor_sync(0xffffffffu, v, o);
    if (lane == 0) out[n] = v + fcb[0];
}

// ---------------- side stream for fork-join overlap -------------------------
struct SideStream {
    cudaStream_t s = 0;
    cudaEvent_t e_fork = 0, e_join = 0;
    SideStream() {
        if (cudaStreamCreateWithFlags(&s, cudaStreamNonBlocking) != cudaSuccess) s = 0;
        cudaEventCreateWithFlags(&e_fork, cudaEventDisableTiming);
        cudaEventCreateWithFlags(&e_join, cudaEventDisableTiming);
    }
};
static SideStream g_side;

// ---------------- launch -----------------------------------------------------
extern "C" void kernel_launch(void* const* d_in, const int* in_sizes, int n_in,
                              void* d_out, int out_size) {
    const float* x   = (const float*)d_in[0];
    const void*  ei  = d_in[1];
    const float* W1  = (const float*)d_in[2];
    const float* b1  = (const float*)d_in[3];
    const float* W2  = (const float*)d_in[4];
    const float* b2  = (const float*)d_in[5];
    const float* fcW = (const float*)d_in[6];
    const float* fcb = (const float*)d_in[7];
    const float* g1  = (const float*)d_in[8];
    const float* be1 = (const float*)d_in[9];
    const float* rm1 = (const float*)d_in[10];
    const float* rv1 = (const float*)d_in[11];
    const float* g2  = (const float*)d_in[12];
    const float* be2 = (const float*)d_in[13];
    const float* rm2 = (const float*)d_in[14];
    const float* rv2 = (const float*)d_in[15];
    float* out = (float*)d_out;

    bool fork = (g_side.s != 0 && g_side.e_fork != 0 && g_side.e_join != 0);
    cudaStream_t sb = fork ? g_side.s : (cudaStream_t)0;

    if (fork) {
        cudaEventRecord(g_side.e_fork, 0);
        cudaStreamWaitEvent(sb, g_side.e_fork, 0);
    }
    // Branch B (side stream): GEMM1, independent of the edge pipeline.
    gemm1_kernel<<<(N_NODES + 63) / 64, 256, 0, sb>>>(x, W1);

    // Branch A (main stream): edge preprocessing chain (4 launches).
    k0_kernel<<<NB + 1, 256>>>((const unsigned int*)ei, b1, rm1, rv1, g1, be1,
                               b2, rm2, rv2, g2, be2);
    convert_kernel<<<EBLK, 256>>>(ei);
    scan1_kernel<<<NB, 256>>>();
    build_kernel<<<EBLK, 256>>>(ei);

    if (fork) {
        cudaEventRecord(g_side.e_join, sb);
        cudaStreamWaitEvent((cudaStream_t)0, g_side.e_join, 0);
    }
    // Joined: aggregation + layer 2 + output.
    agg1_kernel<<<(N_NODES * 32 + 255) / 256, 256>>>();
    gemm2_kernel<<<(N_NODES + 63) / 64, 256>>>(W2);
    agg2_final_kernel<<<(N_NODES * 32 + 255) / 256, 256>>>(fcW, fcb, out);
}

// round 16
// speedup vs baseline: 1.0150x; 1.0150x over previous
#include <cuda_runtime.h>
#include <cuda_fp16.h>

#define N_NODES 50000
#define N_EDGES 800000
#define IN_CH   128
#define HID     64
#define HID2    32
#define NB      196                        // scan blocks (256 nodes each)
#define EBLK    3125                       // edge blocks of 256

// ---------------- scratch (device globals; no allocations allowed) ----------
__device__ int      g_cnt  [N_NODES];
__device__ int      g_lex  [N_NODES];
__device__ int      g_bsum [NB];
__device__ int      g_start[N_NODES];
__device__ int      g_rank [N_EDGES];      // edge rank within its target bucket
__device__ unsigned g_csr  [N_EDGES];      // {src:16 | fp16(dinv[src]):16}
__device__ int      g_is64;
__device__ __half2  g_h1h [N_NODES * 32];  // raw x @ W1, fp16 (64 ch as 32 half2)
__device__ __half2  g_a1h [N_NODES * 32];  // agg1 output, fp16 (64 ch as 32 half2)
__device__ __half2  g_h2h [N_NODES * 16];  // (h2 * dinv), fp16 (32 ch as 16 half2)
__device__ float    g_s1[HID],  g_t1[HID]; // folded bias+BN affine, layer 1
__device__ float    g_s2[HID2], g_t2[HID2];

// ---------------- K0: detect dtype + zero counts + folded BN affines --------
// NOTE: zeroing g_cnt here (immediately before convert's atomics) keeps the
// array L2-resident and dirty — tail-zeroing it elsewhere cost ~45us (R5/R6).
__global__ __launch_bounds__(256) void k0_kernel(const unsigned int* __restrict__ w,
    const float* __restrict__ b1, const float* __restrict__ rm1,
    const float* __restrict__ rv1, const float* __restrict__ g1,
    const float* __restrict__ be1,
    const float* __restrict__ b2, const float* __restrict__ rm2,
    const float* __restrict__ rv2, const float* __restrict__ g2,
    const float* __restrict__ be2) {
    int bb = blockIdx.x;
    if (bb == NB) {   // int64 indices in [0,50000) have zero high words
        __shared__ int cnt;
        if (threadIdx.x == 0) cnt = 0;
        __syncthreads();
        int local = 0;
        for (int i = threadIdx.x; i < 2048; i += 256)
            if (w[2 * i + 1] != 0u) local++;
        atomicAdd(&cnt, local);
        __syncthreads();
        if (threadIdx.x == 0) g_is64 = (cnt < 100) ? 1 : 0;
        return;
    }
    int i = bb * 256 + threadIdx.x;
    if (i < N_NODES) g_cnt[i] = 0;
    if (bb == 0) {
        int t = threadIdx.x;
        if (t < HID) {
            float s = g1[t] * rsqrtf(rv1[t] + 1e-5f);
            g_s1[t] = s;
            g_t1[t] = (b1[t] - rm1[t]) * s + be1[t];
        } else if (t < HID + HID2) {
            int c = t - HID;
            float s = g2[c] * rsqrtf(rv2[c] + 1e-5f);
            g_s2[c] = s;
            g_t2[c] = (b2[c] - rm2[c]) * s + be2[c];
        }
    }
}

// ---------------- histogram over target nodes + per-edge rank ---------------
__global__ __launch_bounds__(256) void convert_kernel(const void* __restrict__ ei) {
    int e = blockIdx.x * 256 + threadIdx.x;
    if (e >= N_EDGES) return;
    int c = g_is64 ? (int)((const long long*)ei)[N_EDGES + e]
                   : ((const int*)ei)[N_EDGES + e];
    g_rank[e] = atomicAdd(&g_cnt[c], 1);
}

// ---------------- scan1: per-block exclusive scan (warp shuffles) -----------
__global__ __launch_bounds__(256) void scan1_kernel() {
    __shared__ int wsum[8];
    int tid = threadIdx.x;
    int lane = tid & 31, wrp = tid >> 5;
    int i = blockIdx.x * 256 + tid;
    int v = (i < N_NODES) ? g_cnt[i] : 0;
    int s = v;
#pragma unroll
    for (int off = 1; off < 32; off <<= 1) {
        int u = __shfl_up_sync(0xffffffffu, s, off);
        if (lane >= off) s += u;
    }
    if (lane == 31) wsum[wrp] = s;
    __syncthreads();
    if (tid < 32) {
        int ws_ = (tid < 8) ? wsum[tid] : 0;
#pragma unroll
        for (int off = 1; off < 8; off <<= 1) {
            int u = __shfl_up_sync(0xffffffffu, ws_, off);
            if (tid >= off) ws_ += u;
        }
        if (tid < 8) wsum[tid] = ws_;
    }
    __syncthreads();
    int incl = s + (wrp > 0 ? wsum[wrp - 1] : 0);
    if (i < N_NODES) g_lex[i] = incl - v;
    if (tid == 255) g_bsum[blockIdx.x] = incl;
}

// ---------------- build: atomic-free CSR placement + start persist ----------
__global__ __launch_bounds__(256) void build_kernel(const void* __restrict__ ei) {
    __shared__ int s[256];
    int t = threadIdx.x;
    s[t] = (t < NB) ? g_bsum[t] : 0;
    __syncthreads();
#pragma unroll
    for (int off = 1; off < 256; off <<= 1) {
        int u = (t >= off) ? s[t - off] : 0;
        __syncthreads();
        s[t] += u;
        __syncthreads();
    }
    if (blockIdx.x < NB) {
        int i = blockIdx.x * 256 + t;
        if (i < N_NODES) {
            int boff = (blockIdx.x == 0) ? 0 : s[blockIdx.x - 1];
            g_start[i] = g_lex[i] + boff;
        }
    }
    int e = blockIdx.x * 256 + t;
    if (e >= N_EDGES) return;
    int r, c;
    if (g_is64) {
        const long long* p = (const long long*)ei;
        r = (int)p[e];
        c = (int)p[N_EDGES + e];
    } else {
        const int* p = (const int*)ei;
        r = p[e];
        c = p[N_EDGES + e];
    }
    int cb = c >> 8;
    int start = g_lex[c] + (cb ? s[cb - 1] : 0);
    __half wh = __float2half(rsqrtf(1.0f + (float)g_cnt[r]));
    unsigned packed = ((unsigned)r << 16) | (unsigned)__half_as_ushort(wh);
    g_csr[start + g_rank[e]] = packed;
}

// ---------------- GEMM1: h1h = fp16(x @ W1)  (side stream) ------------------
// BM=64 BN=64 BK=32, 256 threads, 4x4 microtile. xst padded to 65 cols.
__global__ __launch_bounds__(256) void gemm1_kernel(const float* __restrict__ x,
                                                    const float* __restrict__ W1) {
    __shared__ float xst[32][65];
    __shared__ float ws [32][64];
    int tid = threadIdx.x;
    int tx = tid & 15, ty = tid >> 4;
    int m0 = blockIdx.x * 64;
    float acc[4][4] = {};

    for (int kb = 0; kb < 4; kb++) {
#pragma unroll
        for (int q = 0; q < 2; q++) {
            int id = tid + q * 256;
            int ml = id >> 3;
            int k4 = id & 7;
            int row = m0 + ml;
            float4 v = make_float4(0.f, 0.f, 0.f, 0.f);
            if (row < N_NODES)
                v = *(const float4*)&x[row * IN_CH + kb * 32 + k4 * 4];
            xst[k4 * 4 + 0][ml] = v.x;
            xst[k4 * 4 + 1][ml] = v.y;
            xst[k4 * 4 + 2][ml] = v.z;
            xst[k4 * 4 + 3][ml] = v.w;
        }
#pragma unroll
        for (int q = 0; q < 2; q++) {
            int id = tid + q * 256;
            int kl = id >> 4;
            int n4 = id & 15;
            *(float4*)&ws[kl][n4 * 4] =
                *(const float4*)&W1[(kb * 32 + kl) * HID + n4 * 4];
        }
        __syncthreads();
#pragma unroll
        for (int kk = 0; kk < 32; kk++) {
            float av[4], bv[4];
            av[0] = xst[kk][ty * 4 + 0];
            av[1] = xst[kk][ty * 4 + 1];
            av[2] = xst[kk][ty * 4 + 2];
            av[3] = xst[kk][ty * 4 + 3];
            *(float4*)bv = *(const float4*)&ws[kk][tx * 4];
#pragma unroll
            for (int i = 0; i < 4; i++)
#pragma unroll
                for (int j = 0; j < 4; j++)
                    acc[i][j] += av[i] * bv[j];
        }
        __syncthreads();
    }
#pragma unroll
    for (int i = 0; i < 4; i++) {
        int row = m0 + ty * 4 + i;
        if (row < N_NODES) {
            __half2 a01 = __floats2half2_rn(acc[i][0], acc[i][1]);
            __half2 a23 = __floats2half2_rn(acc[i][2], acc[i][3]);
            *(uint2*)&g_h1h[row * 32 + tx * 2] =
                make_uint2(*(unsigned int*)&a01, *(unsigned int*)&a23);
        }
    }
}

// ---------------- agg1: weighted fp16 gather over packed CSR ----------------
// One warp per node; lane owns 2 channels (one half2). 8 edges in flight.
// Output stored fp16 (one half2 per lane, coalesced 128B per warp).
__global__ __launch_bounds__(256) void agg1_kernel() {
    int n = (blockIdx.x * 256 + threadIdx.x) >> 5;
    int lane = threadIdx.x & 31;
    if (n >= N_NODES) return;
    int start = g_start[n];
    int deg   = g_cnt[n];
    float dn  = rsqrtf(1.0f + (float)deg);
    const __half2* __restrict__ h = g_h1h;
    float2 s = __half22float2(h[n * 32 + lane]);
    float2 acc = make_float2(s.x * dn, s.y * dn);
    int j = 0;
    for (; j + 8 <= deg; j += 8) {
        unsigned e0 = g_csr[start + j];
        unsigned e1 = g_csr[start + j + 1];
        unsigned e2 = g_csr[start + j + 2];
        unsigned e3 = g_csr[start + j + 3];
        unsigned e4 = g_csr[start + j + 4];
        unsigned e5 = g_csr[start + j + 5];
        unsigned e6 = g_csr[start + j + 6];
        unsigned e7 = g_csr[start + j + 7];
        float2 v0 = __half22float2(h[(e0 >> 16) * 32 + lane]);
        float2 v1 = __half22float2(h[(e1 >> 16) * 32 + lane]);
        float2 v2 = __half22float2(h[(e2 >> 16) * 32 + lane]);
        float2 v3 = __half22float2(h[(e3 >> 16) * 32 + lane]);
        float2 v4 = __half22float2(h[(e4 >> 16) * 32 + lane]);
        float2 v5 = __half22float2(h[(e5 >> 16) * 32 + lane]);
        float2 v6 = __half22float2(h[(e6 >> 16) * 32 + lane]);
        float2 v7 = __half22float2(h[(e7 >> 16) * 32 + lane]);
        float w0 = __half2float(__ushort_as_half((unsigned short)e0));
        float w1 = __half2float(__ushort_as_half((unsigned short)e1));
        float w2 = __half2float(__ushort_as_half((unsigned short)e2));
        float w3 = __half2float(__ushort_as_half((unsigned short)e3));
        float w4 = __half2float(__ushort_as_half((unsigned short)e4));
        float w5 = __half2float(__ushort_as_half((unsigned short)e5));
        float w6 = __half2float(__ushort_as_half((unsigned short)e6));
        float w7 = __half2float(__ushort_as_half((unsigned short)e7));
        acc.x += v0.x * w0 + v1.x * w1 + v2.x * w2 + v3.x * w3 +
                 v4.x * w4 + v5.x * w5 + v6.x * w6 + v7.x * w7;
        acc.y += v0.y * w0 + v1.y * w1 + v2.y * w2 + v3.y * w3 +
                 v4.y * w4 + v5.y * w5 + v6.y * w6 + v7.y * w7;
    }
    for (; j + 4 <= deg; j += 4) {
        unsigned e0 = g_csr[start + j];
        unsigned e1 = g_csr[start + j + 1];
        unsigned e2 = g_csr[start + j + 2];
        unsigned e3 = g_csr[start + j + 3];
        float2 v0 = __half22float2(h[(e0 >> 16) * 32 + lane]);
        float2 v1 = __half22float2(h[(e1 >> 16) * 32 + lane]);
        float2 v2 = __half22float2(h[(e2 >> 16) * 32 + lane]);
        float2 v3 = __half22float2(h[(e3 >> 16) * 32 + lane]);
        float w0 = __half2float(__ushort_as_half((unsigned short)e0));
        float w1 = __half2float(__ushort_as_half((unsigned short)e1));
        float w2 = __half2float(__ushort_as_half((unsigned short)e2));
        float w3 = __half2float(__ushort_as_half((unsigned short)e3));
        acc.x += v0.x * w0 + v1.x * w1 + v2.x * w2 + v3.x * w3;
        acc.y += v0.y * w0 + v1.y * w1 + v2.y * w2 + v3.y * w3;
    }
    for (; j < deg; j++) {
        unsigned e = g_csr[start + j];
        float2 v = __half22float2(h[(e >> 16) * 32 + lane]);
        float w = __half2float(__ushort_as_half((unsigned short)e));
        acc.x += v.x * w;
        acc.y += v.y * w;
    }
    g_a1h[n * 32 + lane] = __floats2half2_rn(acc.x * dn, acc.y * dn);
}

// ---------------- GEMM2: h2h = fp16((relu(a1h*s1+t1) @ W2) * dinv) ----------
// ast padded to 65 cols; agg1 input fp16 (uint2 = 4 channels per load).
__global__ __launch_bounds__(256) void gemm2_kernel(const float* __restrict__ W2) {
    __shared__ float ast[64][65];
    __shared__ float w2s[64][32];
    int tid = threadIdx.x;
    int tx = tid & 15, ty = tid >> 4;
    int m0 = blockIdx.x * 64;

#pragma unroll
    for (int q = 0; q < 4; q++) {
        int id = tid + q * 256;            // 1024 loads: 64 rows x 16 uint2
        int ml = id >> 4;
        int k4 = id & 15;                  // 4 channels per uint2
        int row = m0 + ml;
        float v[4] = {0.f, 0.f, 0.f, 0.f};
        if (row < N_NODES) {
            uint2 u = *(const uint2*)&g_a1h[row * 32 + k4 * 2];
            float2 f01 = __half22float2(*(__half2*)&u.x);
            float2 f23 = __half22float2(*(__half2*)&u.y);
            v[0] = f01.x; v[1] = f01.y; v[2] = f23.x; v[3] = f23.y;
        }
#pragma unroll
        for (int i = 0; i < 4; i++) {
            int k = k4 * 4 + i;
            float z = fmaxf(v[i] * g_s1[k] + g_t1[k], 0.0f);
            ast[k][ml] = (row < N_NODES) ? z : 0.0f;
        }
    }
#pragma unroll
    for (int q = 0; q < 2; q++) {
        int id = tid + q * 256;
        int kl = id >> 3;
        int n4 = id & 7;
        *(float4*)&w2s[kl][n4 * 4] = *(const float4*)&W2[kl * HID2 + n4 * 4];
    }
    __syncthreads();

    float acc[4][2] = {};
#pragma unroll
    for (int kk = 0; kk < 64; kk++) {
        float av[4], bv[2];
        av[0] = ast[kk][ty * 4 + 0];
        av[1] = ast[kk][ty * 4 + 1];
        av[2] = ast[kk][ty * 4 + 2];
        av[3] = ast[kk][ty * 4 + 3];
        *(float2*)bv = *(const float2*)&w2s[kk][tx * 2];
#pragma unroll
        for (int i = 0; i < 4; i++) {
            acc[i][0] += av[i] * bv[0];
            acc[i][1] += av[i] * bv[1];
        }
    }
#pragma unroll
    for (int i = 0; i < 4; i++) {
        int row = m0 + ty * 4 + i;
        if (row < N_NODES) {
            float d = rsqrtf(1.0f + (float)g_cnt[row]);
            g_h2h[row * 16 + tx] = __floats2half2_rn(acc[i][0] * d, acc[i][1] * d);
        }
    }
}

// ---------------- agg2 + BN/ReLU + fc, fused --------------------------------
// One warp per node; lane owns 1 channel (__half loads); 8 edges in flight.
__global__ __launch_bounds__(256) void agg2_final_kernel(const float* __restrict__ fcW,
                                                         const float* __restrict__ fcb,
                                                         float* __restrict__ out) {
    int n = (blockIdx.x * 256 + threadIdx.x) >> 5;
    int lane = threadIdx.x & 31;
    if (n >= N_NODES) return;
    int start = g_start[n];
    int deg   = g_cnt[n];
    const __half* __restrict__ h = (const __half*)g_h2h;
    float acc = __half2float(h[n * 32 + lane]);   // self (already *dinv)
    int j = 0;
    for (; j + 8 <= deg; j += 8) {
        unsigned e0 = g_csr[start + j];
        unsigned e1 = g_csr[start + j + 1];
        unsigned e2 = g_csr[start + j + 2];
        unsigned e3 = g_csr[start + j + 3];
        unsigned e4 = g_csr[start + j + 4];
        unsigned e5 = g_csr[start + j + 5];
        unsigned e6 = g_csr[start + j + 6];
        unsigned e7 = g_csr[start + j + 7];
        acc += ((__half2float(h[(e0 >> 16) * 32 + lane]) + __half2float(h[(e1 >> 16) * 32 + lane])) +
                (__half2float(h[(e2 >> 16) * 32 + lane]) + __half2float(h[(e3 >> 16) * 32 + lane]))) +
               ((__half2float(h[(e4 >> 16) * 32 + lane]) + __half2float(h[(e5 >> 16) * 32 + lane])) +
                (__half2float(h[(e6 >> 16) * 32 + lane]) + __half2float(h[(e7 >> 16) * 32 + lane])));
    }
    for (; j + 4 <= deg; j += 4) {
        unsigned e0 = g_csr[start + j];
        unsigned e1 = g_csr[start + j + 1];
        unsigned e2 = g_csr[start + j + 2];
        unsigned e3 = g_csr[start + j + 3];
        acc += (__half2float(h[(e0 >> 16) * 32 + lane]) + __half2float(h[(e1 >> 16) * 32 + lane])) +
               (__half2float(h[(e2 >> 16) * 32 + lane]) + __half2float(h[(e3 >> 16) * 32 + lane]));
    }
    for (; j < deg; j++)
        acc += __half2float(h[(g_csr[start + j] >> 16) * 32 + lane]);
    float agg = acc * rsqrtf(1.0f + (float)deg);
    float v = fmaxf(agg * g_s2[lane] + g_t2[lane], 0.0f) * fcW[lane];
#pragma unroll
    for (int o = 16; o > 0; o >>= 1)
        v += __shfl_xor_sync(0xffffffffu, v, o);
    if (lane == 0) out[n] = v + fcb[0];
}

// ---------------- side stream for fork-join overlap -------------------------
struct SideStream {
    cudaStream_t s = 0;
    cudaEvent_t e_fork = 0, e_join = 0;
    SideStream() {
        if (cudaStreamCreateWithFlags(&s, cudaStreamNonBlocking) != cudaSuccess) s = 0;
        cudaEventCreateWithFlags(&e_fork, cudaEventDisableTiming);
        cudaEventCreateWithFlags(&e_join, cudaEventDisableTiming);
    }
};
static SideStream g_side;

// ---------------- launch -----------------------------------------------------
extern "C" void kernel_launch(void* const* d_in, const int* in_sizes, int n_in,
                              void* d_out, int out_size) {
    const float* x   = (const float*)d_in[0];
    const void*  ei  = d_in[1];
    const float* W1  = (const float*)d_in[2];
    const float* b1  = (const float*)d_in[3];
    const float* W2  = (const float*)d_in[4];
    const float* b2  = (const float*)d_in[5];
    const float* fcW = (const float*)d_in[6];
    const float* fcb = (const float*)d_in[7];
    const float* g1  = (const float*)d_in[8];
    const float* be1 = (const float*)d_in[9];
    const float* rm1 = (const float*)d_in[10];
    const float* rv1 = (const float*)d_in[11];
    const float* g2  = (const float*)d_in[12];
    const float* be2 = (const float*)d_in[13];
    const float* rm2 = (const float*)d_in[14];
    const float* rv2 = (const float*)d_in[15];
    float* out = (float*)d_out;

    bool fork = (g_side.s != 0 && g_side.e_fork != 0 && g_side.e_join != 0);
    cudaStream_t sb = fork ? g_side.s : (cudaStream_t)0;

    if (fork) {
        cudaEventRecord(g_side.e_fork, 0);
        cudaStreamWaitEvent(sb, g_side.e_fork, 0);
    }
    // Branch B (side stream): GEMM1, independent of the edge pipeline.
    gemm1_kernel<<<(N_NODES + 63) / 64, 256, 0, sb>>>(x, W1);

    // Branch A (main stream): edge preprocessing chain (4 launches).
    k0_kernel<<<NB + 1, 256>>>((const unsigned int*)ei, b1, rm1, rv1, g1, be1,
                               b2, rm2, rv2, g2, be2);
    convert_kernel<<<EBLK, 256>>>(ei);
    scan1_kernel<<<NB, 256>>>();
    build_kernel<<<EBLK, 256>>>(ei);

    if (fork) {
        cudaEventRecord(g_side.e_join, sb);
        cudaStreamWaitEvent((cudaStream_t)0, g_side.e_join, 0);
    }
    // Joined: aggregation + layer 2 + output.
    agg1_kernel<<<(N_NODES * 32 + 255) / 256, 256>>>();
    gemm2_kernel<<<(N_NODES + 63) / 64, 256>>>(W2);
    agg2_final_kernel<<<(N_NODES * 32 + 255) / 256, 256>>>(fcW, fcb, out);
}